// round 1
// baseline (speedup 1.0000x reference)
#include <cuda_runtime.h>
#include <stdint.h>

// Problem constants (fixed by the reference: NX=41, r_max=6.0, voxel=0.3, K=4, min_sep=3)
#define NXG    41
#define NROWS  (NXG * NXG)      // 1681 rows of 41 voxels
#define GVOX   (NXG * NXG * NXG) // 68921
#define KP     4
#define SEP    3
#define NEGF   (-1.0e9f)
#define VTH    (-1.0e8f)

// Precomputed sphere mask (1 byte per voxel, 69 KB -> L2 resident). Scratch via
// __device__ global (no allocation allowed).
__device__ uint8_t g_sphere_mask[GVOX];

// Build sphere mask EXACTLY as numpy: norm = sqrt(((x*x + y*y) + z*z)) in f32,
// compare <= 6.0f. Forced-rounding intrinsics prevent fma contraction.
__global__ void build_mask_kernel(const float* __restrict__ grid_xyz) {
    int g = blockIdx.x * blockDim.x + threadIdx.x;
    if (g >= GVOX) return;
    float x = grid_xyz[3 * g + 0];
    float y = grid_xyz[3 * g + 1];
    float z = grid_xyz[3 * g + 2];
    float s = __fadd_rn(__fadd_rn(__fmul_rn(x, x), __fmul_rn(y, y)), __fmul_rn(z, z));
    g_sphere_mask[g] = (__fsqrt_rn(s) <= 6.0f) ? (uint8_t)1 : (uint8_t)0;
}

// One CTA per (n,c) problem. 256 threads = 8 warps, warp-per-row loads.
__global__ __launch_bounds__(256, 4)
void peaks_kernel(const float* __restrict__ density,
                  const float* __restrict__ grid_xyz,
                  const float* __restrict__ Rmats,
                  const float* __restrict__ tpos,
                  const float* __restrict__ node_mask,
                  float* __restrict__ out,
                  int C)
{
    __shared__ float   rowmax[NROWS];
    __shared__ uint8_t rowk[NROWS];
    __shared__ float   swv[8];
    __shared__ int     swr[8];
    __shared__ int     s_pick_row;
    __shared__ float   s_peak_s[KP];
    __shared__ int     s_peak_g[KP];
    __shared__ int     s_peak_valid[KP];

    const int tid  = threadIdx.x;
    const int lane = tid & 31;
    const int w    = tid >> 5;
    const size_t base = (size_t)blockIdx.x * GVOX;

    // ---------------- Phase 1: per-row max over the full grid ----------------
    // Warp handles one row (41 contiguous floats): lane reads k=lane and k=lane+32.
    for (int r = w; r < NROWS; r += 8) {
        const int gb = r * NXG;
        float v = g_sphere_mask[gb + lane] ? __ldg(&density[base + gb + lane]) : NEGF;
        int   k = lane;
        const int k2 = lane + 32;
        if (k2 < NXG) {
            float v2 = g_sphere_mask[gb + k2] ? __ldg(&density[base + gb + k2]) : NEGF;
            if (v2 > v) { v = v2; k = k2; }   // strict > keeps lower k on tie
        }
        #pragma unroll
        for (int off = 16; off; off >>= 1) {
            float ov = __shfl_xor_sync(0xffffffffu, v, off);
            int   ok = __shfl_xor_sync(0xffffffffu, k, off);
            if (ov > v || (ov == v && ok < k)) { v = ov; k = ok; }
        }
        if (lane == 0) { rowmax[r] = v; rowk[r] = (uint8_t)k; }
    }
    __syncthreads();

    // ---------------- K iterations: argmax over row table + local NMS --------
    int pk_i[KP], pk_j[KP], pk_k[KP];
    int npk = 0;  // replicated across all threads (derived from shared data)

    for (int it = 0; it < KP; it++) {
        // Block argmax over rowmax[0..1680], first-occurrence tie-break.
        float bv = -__int_as_float(0x7f800000); // -inf
        int   br = 0x7fffffff;
        for (int r = tid; r < NROWS; r += 256) {
            float v = rowmax[r];
            if (v > bv) { bv = v; br = r; }     // r increasing: ties keep earlier
        }
        #pragma unroll
        for (int off = 16; off; off >>= 1) {
            float ov = __shfl_xor_sync(0xffffffffu, bv, off);
            int   orr = __shfl_xor_sync(0xffffffffu, br, off);
            if (ov > bv || (ov == bv && orr < br)) { bv = ov; br = orr; }
        }
        if (lane == 0) { swv[w] = bv; swr[w] = br; }
        __syncthreads();
        if (w == 0) {
            float v = (lane < 8) ? swv[lane] : -__int_as_float(0x7f800000);
            int   r = (lane < 8) ? swr[lane] : 0x7fffffff;
            #pragma unroll
            for (int off = 4; off; off >>= 1) {
                float ov = __shfl_xor_sync(0xffffffffu, v, off);
                int   orr = __shfl_xor_sync(0xffffffffu, r, off);
                if (ov > v || (ov == v && orr < r)) { v = ov; r = orr; }
            }
            if (lane == 0) s_pick_row = r;
        }
        __syncthreads();

        const int   pr  = s_pick_row;
        const float sc  = rowmax[pr];
        const int   pkk = (int)rowk[pr];
        const int   pi  = pr / NXG;
        const int   pj  = pr % NXG;
        const bool  valid = sc > VTH;

        if (tid == 0) {
            s_peak_s[it]     = sc;
            s_peak_g[it]     = pr * NXG + pkk;
            s_peak_valid[it] = valid ? 1 : 0;
        }
        if (valid) { pk_i[npk] = pi; pk_j[npk] = pj; pk_k[npk] = pkk; npk++; }
        __syncthreads();   // everyone done reading rowmax before rewrite

        if (it == KP - 1) break;

        // Recompute rows intersecting the new peak's Chebyshev ball, applying
        // suppression from ALL picked-so-far peaks (rows may overlap balls).
        if (valid) {
            const int i0 = max(pi - SEP, 0), i1 = min(pi + SEP, NXG - 1);
            const int j0 = max(pj - SEP, 0), j1 = min(pj + SEP, NXG - 1);
            const int ni = i1 - i0 + 1, nj = j1 - j0 + 1, nr = ni * nj;
            for (int q = w; q < nr; q += 8) {
                const int i = i0 + q / nj;
                const int j = j0 + q % nj;
                const int r = i * NXG + j;
                const int gb = r * NXG;

                float v = NEGF; int k = lane;
                {
                    const int kk = lane;
                    bool sup = (g_sphere_mask[gb + kk] == 0);
                    #pragma unroll
                    for (int p = 0; p < KP; p++) {
                        if (p < npk &&
                            abs(i - pk_i[p]) <= SEP && abs(j - pk_j[p]) <= SEP &&
                            abs(kk - pk_k[p]) <= SEP) sup = true;
                    }
                    if (!sup) v = __ldg(&density[base + gb + kk]);
                }
                const int kk2 = lane + 32;
                if (kk2 < NXG) {
                    bool sup = (g_sphere_mask[gb + kk2] == 0);
                    #pragma unroll
                    for (int p = 0; p < KP; p++) {
                        if (p < npk &&
                            abs(i - pk_i[p]) <= SEP && abs(j - pk_j[p]) <= SEP &&
                            abs(kk2 - pk_k[p]) <= SEP) sup = true;
                    }
                    if (!sup) {
                        float v2 = __ldg(&density[base + gb + kk2]);
                        if (v2 > v) { v = v2; k = kk2; }
                    }
                }
                #pragma unroll
                for (int off = 16; off; off >>= 1) {
                    float ov = __shfl_xor_sync(0xffffffffu, v, off);
                    int   ok = __shfl_xor_sync(0xffffffffu, k, off);
                    if (ov > v || (ov == v && ok < k)) { v = ov; k = ok; }
                }
                if (lane == 0) { rowmax[r] = v; rowk[r] = (uint8_t)k; }
            }
        }
        __syncthreads();
    }

    // ---------------- Epilogue: transform + write outputs --------------------
    // Output layout: coords_local [NC,K,3] | coords_global [NC,K,3] |
    //                scores [NC,K] | mask [NC,K]   (all as float32)
    if (tid < KP) {
        const int kk = tid;
        const int p  = blockIdx.x;
        const int n  = p / C;
        const int NC = gridDim.x;

        const float sc    = s_peak_s[kk];
        const bool  valid = (s_peak_valid[kk] != 0);
        const int   g     = s_peak_g[kk];

        float x = 0.f, y = 0.f, z = 0.f;
        if (valid) {
            x = grid_xyz[3 * g + 0];
            y = grid_xyz[3 * g + 1];
            z = grid_xyz[3 * g + 2];
        }
        const float nm = node_mask[n];
        const float* R = Rmats + (size_t)n * 9;
        const float* t = tpos  + (size_t)n * 3;
        const float gx = R[0] * x + R[1] * y + R[2] * z + t[0];
        const float gy = R[3] * x + R[4] * y + R[5] * z + t[1];
        const float gz = R[6] * x + R[7] * y + R[8] * z + t[2];

        float* CL = out;
        float* CG = out + (size_t)NC * KP * 3;
        float* SC = out + (size_t)NC * KP * 6;
        float* MS = SC  + (size_t)NC * KP;

        const size_t o3 = ((size_t)p * KP + kk) * 3;
        CL[o3 + 0] = x * nm;  CL[o3 + 1] = y * nm;  CL[o3 + 2] = z * nm;
        CG[o3 + 0] = gx * nm; CG[o3 + 1] = gy * nm; CG[o3 + 2] = gz * nm;
        SC[(size_t)p * KP + kk] = (valid ? sc : NEGF) * nm;
        MS[(size_t)p * KP + kk] = (valid && nm != 0.0f) ? 1.0f : 0.0f;
    }
}

extern "C" void kernel_launch(void* const* d_in, const int* in_sizes, int n_in,
                              void* d_out, int out_size)
{
    // Input order per reference setup_inputs():
    // 0: density [B,N,C,G] f32   1: grid_xyz [G,3] f32   2: sphere_mask [G] (unused)
    // 3: coords_int [G,3] (unused)  4: Rmats [B,N,3,3] f32  5: tpos [B,N,3] f32
    // 6: node_mask [B,N] f32
    const float* density   = (const float*)d_in[0];
    const float* grid_xyz  = (const float*)d_in[1];
    const float* Rmats     = (const float*)d_in[4];
    const float* tposp     = (const float*)d_in[5];
    const float* node_mask = (const float*)d_in[6];
    float* out = (float*)d_out;

    const int NC = in_sizes[0] / GVOX;      // B*N*C = 512
    const int N  = in_sizes[4] / 9;         // B*N   = 128
    const int C  = NC / N;                  // 4
    (void)n_in; (void)out_size;

    build_mask_kernel<<<(GVOX + 255) / 256, 256>>>(grid_xyz);
    peaks_kernel<<<NC, 256>>>(density, grid_xyz, Rmats, tposp, node_mask, out, C);
}

// round 2
// speedup vs baseline: 2.1686x; 2.1686x over previous
#include <cuda_runtime.h>
#include <stdint.h>

// Problem constants (fixed by the reference: NX=41, r_max=6.0, voxel=0.3, K=4, min_sep=3)
#define NXG    41
#define NROWS  (NXG * NXG)       // 1681 rows of 41 voxels
#define GVOX   (NXG * NXG * NXG) // 68921
#define KP     4
#define SEP    3
#define NEGF   (-1.0e9f)
#define VTH    (-1.0e8f)

#define ROWS_PER_BLK 256
#define NBLK_ROWS    ((NROWS + ROWS_PER_BLK - 1) / ROWS_PER_BLK)  // 7

#define MAX_NC 1024   // cap on B*N*C problems (dataset: 512)

// Scratch via __device__ globals (no allocation allowed).
__device__ uint8_t g_sphere_mask[GVOX];
__device__ float   g_rowmax[MAX_NC * NROWS];
__device__ uint8_t g_rowk  [MAX_NC * NROWS];

// ---------------------------------------------------------------------------
// Build sphere mask EXACTLY as numpy: norm = sqrt((x*x + y*y) + z*z) in f32,
// compare <= 6.0f. Forced-rounding intrinsics prevent fma contraction.
__global__ void build_mask_kernel(const float* __restrict__ grid_xyz) {
    int g = blockIdx.x * blockDim.x + threadIdx.x;
    if (g >= GVOX) return;
    float x = grid_xyz[3 * g + 0];
    float y = grid_xyz[3 * g + 1];
    float z = grid_xyz[3 * g + 2];
    float s = __fadd_rn(__fadd_rn(__fmul_rn(x, x), __fmul_rn(y, y)), __fmul_rn(z, z));
    g_sphere_mask[g] = (__fsqrt_rn(s) <= 6.0f) ? (uint8_t)1 : (uint8_t)0;
}

// ---------------------------------------------------------------------------
// Kernel A: streaming per-row (masked) max + argmax over the full density.
// grid = (NC, 7). Block stages 256 rows (42 KB) coalesced into SMEM, applies
// the sphere mask at stage time (exact NEGF sentinel like the reference),
// then each thread serially arg-reduces one row from SMEM (stride 41 words
// across lanes -> conflict-free since gcd(41,32)=1).
__global__ __launch_bounds__(256)
void rowmax_kernel(const float* __restrict__ density)
{
    __shared__ float sv[ROWS_PER_BLK * NXG];   // 41984 B

    const int p  = blockIdx.x;
    const int r0 = blockIdx.y * ROWS_PER_BLK;
    const int nrows = min(ROWS_PER_BLK, NROWS - r0);
    const int nelem = nrows * NXG;
    const size_t gbase = (size_t)p * GVOX + (size_t)r0 * NXG;
    const int    mbase = r0 * NXG;

    #pragma unroll 4
    for (int idx = threadIdx.x; idx < nelem; idx += 256) {
        float v = __ldg(&density[gbase + idx]);
        sv[idx] = g_sphere_mask[mbase + idx] ? v : NEGF;
    }
    __syncthreads();

    const int t = threadIdx.x;
    if (t < nrows) {
        const float* row = &sv[t * NXG];
        // Two interleaved chains for ILP; merge keeps first-index tie-break.
        float b0 = row[0]; int k0 = 0;
        float b1 = row[1]; int k1 = 1;
        #pragma unroll
        for (int k = 2; k < NXG - 1; k += 2) {
            float v0 = row[k];
            float v1 = row[k + 1];
            if (v0 > b0) { b0 = v0; k0 = k; }
            if (v1 > b1) { b1 = v1; k1 = k + 1; }
        }
        { float v = row[NXG - 1]; if (v > b0) { b0 = v; k0 = NXG - 1; } }
        // merge: ties prefer smaller index
        float best; int bk;
        if (b1 > b0 || (b1 == b0 && k1 < k0)) { best = b1; bk = k1; }
        else                                   { best = b0; bk = k0; }
        g_rowmax[(size_t)p * NROWS + r0 + t] = best;
        g_rowk  [(size_t)p * NROWS + r0 + t] = (uint8_t)bk;
    }
}

// ---------------------------------------------------------------------------
// Kernel B: per-problem iterative argmax + Chebyshev NMS using the row table,
// then transform + output epilogue. One CTA per (n,c), 256 threads = 8 warps.
__global__ __launch_bounds__(256, 4)
void peaks_kernel(const float* __restrict__ density,
                  const float* __restrict__ grid_xyz,
                  const float* __restrict__ Rmats,
                  const float* __restrict__ tpos,
                  const float* __restrict__ node_mask,
                  float* __restrict__ out,
                  int C)
{
    __shared__ float   rowmax[NROWS];
    __shared__ uint8_t rowk[NROWS];
    __shared__ float   swv[8];
    __shared__ int     swr[8];
    __shared__ int     s_pick_row;
    __shared__ float   s_peak_s[KP];
    __shared__ int     s_peak_g[KP];
    __shared__ int     s_peak_valid[KP];

    const int tid  = threadIdx.x;
    const int lane = tid & 31;
    const int w    = tid >> 5;
    const size_t base = (size_t)blockIdx.x * GVOX;

    // Load the precomputed row table (coalesced).
    {
        const size_t tb = (size_t)blockIdx.x * NROWS;
        for (int r = tid; r < NROWS; r += 256) {
            rowmax[r] = g_rowmax[tb + r];
            rowk[r]   = g_rowk[tb + r];
        }
    }
    __syncthreads();

    // ---------------- K iterations: argmax over row table + local NMS --------
    int pk_i[KP], pk_j[KP], pk_k[KP];
    int npk = 0;  // replicated across all threads (derived from shared data)

    for (int it = 0; it < KP; it++) {
        // Block argmax over rowmax[0..1680], first-occurrence tie-break.
        float bv = -__int_as_float(0x7f800000); // -inf
        int   br = 0x7fffffff;
        for (int r = tid; r < NROWS; r += 256) {
            float v = rowmax[r];
            if (v > bv) { bv = v; br = r; }     // r increasing: ties keep earlier
        }
        #pragma unroll
        for (int off = 16; off; off >>= 1) {
            float ov = __shfl_xor_sync(0xffffffffu, bv, off);
            int   orr = __shfl_xor_sync(0xffffffffu, br, off);
            if (ov > bv || (ov == bv && orr < br)) { bv = ov; br = orr; }
        }
        if (lane == 0) { swv[w] = bv; swr[w] = br; }
        __syncthreads();
        if (w == 0) {
            float v = (lane < 8) ? swv[lane] : -__int_as_float(0x7f800000);
            int   r = (lane < 8) ? swr[lane] : 0x7fffffff;
            #pragma unroll
            for (int off = 4; off; off >>= 1) {
                float ov = __shfl_xor_sync(0xffffffffu, v, off);
                int   orr = __shfl_xor_sync(0xffffffffu, r, off);
                if (ov > v || (ov == v && orr < r)) { v = ov; r = orr; }
            }
            if (lane == 0) s_pick_row = r;
        }
        __syncthreads();

        const int   pr  = s_pick_row;
        const float sc  = rowmax[pr];
        const int   pkk = (int)rowk[pr];
        const int   pi  = pr / NXG;
        const int   pj  = pr % NXG;
        const bool  valid = sc > VTH;

        if (tid == 0) {
            s_peak_s[it]     = sc;
            s_peak_g[it]     = pr * NXG + pkk;
            s_peak_valid[it] = valid ? 1 : 0;
        }
        if (valid) { pk_i[npk] = pi; pk_j[npk] = pj; pk_k[npk] = pkk; npk++; }
        __syncthreads();   // everyone done reading rowmax before rewrite

        if (it == KP - 1) break;

        // Recompute rows intersecting the new peak's Chebyshev ball, applying
        // suppression from ALL picked-so-far peaks (rows may overlap balls).
        if (valid) {
            const int i0 = max(pi - SEP, 0), i1 = min(pi + SEP, NXG - 1);
            const int j0 = max(pj - SEP, 0), j1 = min(pj + SEP, NXG - 1);
            const int ni = i1 - i0 + 1, nj = j1 - j0 + 1, nr = ni * nj;
            for (int q = w; q < nr; q += 8) {
                const int i = i0 + q / nj;
                const int j = j0 + q % nj;
                const int r = i * NXG + j;
                const int gb = r * NXG;

                float v = NEGF; int k = lane;
                {
                    const int kk = lane;
                    bool sup = (g_sphere_mask[gb + kk] == 0);
                    #pragma unroll
                    for (int p = 0; p < KP; p++) {
                        if (p < npk &&
                            abs(i - pk_i[p]) <= SEP && abs(j - pk_j[p]) <= SEP &&
                            abs(kk - pk_k[p]) <= SEP) sup = true;
                    }
                    if (!sup) v = __ldg(&density[base + gb + kk]);
                }
                const int kk2 = lane + 32;
                if (kk2 < NXG) {
                    bool sup = (g_sphere_mask[gb + kk2] == 0);
                    #pragma unroll
                    for (int p = 0; p < KP; p++) {
                        if (p < npk &&
                            abs(i - pk_i[p]) <= SEP && abs(j - pk_j[p]) <= SEP &&
                            abs(kk2 - pk_k[p]) <= SEP) sup = true;
                    }
                    if (!sup) {
                        float v2 = __ldg(&density[base + gb + kk2]);
                        if (v2 > v) { v = v2; k = kk2; }
                    }
                }
                #pragma unroll
                for (int off = 16; off; off >>= 1) {
                    float ov = __shfl_xor_sync(0xffffffffu, v, off);
                    int   ok = __shfl_xor_sync(0xffffffffu, k, off);
                    if (ov > v || (ov == v && ok < k)) { v = ov; k = ok; }
                }
                if (lane == 0) { rowmax[r] = v; rowk[r] = (uint8_t)k; }
            }
        }
        __syncthreads();
    }

    // ---------------- Epilogue: transform + write outputs --------------------
    // Output layout: coords_local [NC,K,3] | coords_global [NC,K,3] |
    //                scores [NC,K] | mask [NC,K]   (all as float32)
    if (tid < KP) {
        const int kk = tid;
        const int p  = blockIdx.x;
        const int n  = p / C;
        const int NC = gridDim.x;

        const float sc    = s_peak_s[kk];
        const bool  valid = (s_peak_valid[kk] != 0);
        const int   g     = s_peak_g[kk];

        float x = 0.f, y = 0.f, z = 0.f;
        if (valid) {
            x = grid_xyz[3 * g + 0];
            y = grid_xyz[3 * g + 1];
            z = grid_xyz[3 * g + 2];
        }
        const float nm = node_mask[n];
        const float* R = Rmats + (size_t)n * 9;
        const float* t = tpos  + (size_t)n * 3;
        const float gx = R[0] * x + R[1] * y + R[2] * z + t[0];
        const float gy = R[3] * x + R[4] * y + R[5] * z + t[1];
        const float gz = R[6] * x + R[7] * y + R[8] * z + t[2];

        float* CL = out;
        float* CG = out + (size_t)NC * KP * 3;
        float* SC = out + (size_t)NC * KP * 6;
        float* MS = SC  + (size_t)NC * KP;

        const size_t o3 = ((size_t)p * KP + kk) * 3;
        CL[o3 + 0] = x * nm;  CL[o3 + 1] = y * nm;  CL[o3 + 2] = z * nm;
        CG[o3 + 0] = gx * nm; CG[o3 + 1] = gy * nm; CG[o3 + 2] = gz * nm;
        SC[(size_t)p * KP + kk] = (valid ? sc : NEGF) * nm;
        MS[(size_t)p * KP + kk] = (valid && nm != 0.0f) ? 1.0f : 0.0f;
    }
}

extern "C" void kernel_launch(void* const* d_in, const int* in_sizes, int n_in,
                              void* d_out, int out_size)
{
    // Input order per reference setup_inputs():
    // 0: density [B,N,C,G] f32   1: grid_xyz [G,3] f32   2: sphere_mask [G] (unused)
    // 3: coords_int [G,3] (unused)  4: Rmats [B,N,3,3] f32  5: tpos [B,N,3] f32
    // 6: node_mask [B,N] f32
    const float* density   = (const float*)d_in[0];
    const float* grid_xyz  = (const float*)d_in[1];
    const float* Rmats     = (const float*)d_in[4];
    const float* tposp     = (const float*)d_in[5];
    const float* node_mask = (const float*)d_in[6];
    float* out = (float*)d_out;

    const int NC = in_sizes[0] / GVOX;      // B*N*C = 512
    const int N  = in_sizes[4] / 9;         // B*N   = 128
    const int C  = NC / N;                  // 4
    (void)n_in; (void)out_size;

    build_mask_kernel<<<(GVOX + 255) / 256, 256>>>(grid_xyz);
    dim3 gA(NC, NBLK_ROWS);
    rowmax_kernel<<<gA, 256>>>(density);
    peaks_kernel<<<NC, 256>>>(density, grid_xyz, Rmats, tposp, node_mask, out, C);
}

// round 3
// speedup vs baseline: 2.8875x; 1.3315x over previous
#include <cuda_runtime.h>
#include <stdint.h>

// Problem constants (fixed by the reference: NX=41, r_max=6.0, voxel=0.3, K=4, min_sep=3)
#define NXG    41
#define NROWS  (NXG * NXG)       // 1681 rows of 41 voxels
#define GVOX   (NXG * NXG * NXG) // 68921
#define KP     4
#define SEP    3
#define NEGF   (-1.0e9f)
#define VTH    (-1.0e8f)

#define CHUNK_ROWS 256
#define NCHUNK     7            // ceil(1681/256)

// Shared-memory layout offsets (bytes), all 4-byte aligned.
#define SM_BUF    0                          // CHUNK_ROWS*NXG floats = 41984 B
#define SM_ROWMAX (SM_BUF + CHUNK_ROWS*NXG*4)        // 1681 floats = 6724 B
#define SM_ROWK   (SM_ROWMAX + 6724)                 // 1684 B (padded)
#define SM_XS2    (SM_ROWK + 1684)                   // 41 floats -> 168 B
#define SM_YS2    (SM_XS2 + 168)                     // 168 B
#define SM_ZZ     (SM_YS2 + 168)                     // 168 B
#define SM_SWV    (SM_ZZ + 168)                      // 8 floats -> 32 B
#define SM_SWR    (SM_SWV + 32)                      // 8 ints   -> 32 B
#define SM_PICK   (SM_SWR + 32)                      // 1 int
#define SM_PS     (SM_PICK + 4)                      // KP floats
#define SM_PG     (SM_PS + 16)                       // KP ints
#define SM_PV     (SM_PG + 16)                       // KP ints
#define SM_TOTAL  (SM_PV + 16 + 16)                  // ~51 KB

// ---------------------------------------------------------------------------
// Fully fused: per-problem rowmax build (streamed through SMEM), K-iteration
// argmax + Chebyshev NMS, transform + output epilogue. One CTA per (n,c).
// 512 CTAs x 51KB smem -> 4 CTAs/SM -> single resident wave on 148 SMs.
__global__ __launch_bounds__(256, 4)
void fused_peaks_kernel(const float* __restrict__ density,
                        const float* __restrict__ grid_xyz,
                        const float* __restrict__ Rmats,
                        const float* __restrict__ tpos,
                        const float* __restrict__ node_mask,
                        float* __restrict__ out,
                        int C)
{
    extern __shared__ char smem[];
    float*   buf    = (float*)(smem + SM_BUF);
    float*   rowmax = (float*)(smem + SM_ROWMAX);
    uint8_t* rowk   = (uint8_t*)(smem + SM_ROWK);
    float*   xs2    = (float*)(smem + SM_XS2);
    float*   ys2    = (float*)(smem + SM_YS2);
    float*   zz     = (float*)(smem + SM_ZZ);
    float*   swv    = (float*)(smem + SM_SWV);
    int*     swr    = (int*)(smem + SM_SWR);
    int*     s_pick = (int*)(smem + SM_PICK);
    float*   s_ps   = (float*)(smem + SM_PS);
    int*     s_pg   = (int*)(smem + SM_PG);
    int*     s_pv   = (int*)(smem + SM_PV);

    const int tid  = threadIdx.x;
    const int lane = tid & 31;
    const int w    = tid >> 5;
    const size_t base = (size_t)blockIdx.x * GVOX;

    // Per-axis squared-coordinate tables from the ACTUAL grid_xyz input.
    // Rows are axis-aligned: x depends only on i, y only on j, z only on k.
    // Sphere test (s<=36.0f) is bit-equivalent to sqrtf(s)<=6.0f under RN.
    if (tid < NXG) {
        float x = grid_xyz[3 * (tid * NXG * NXG) + 0];
        float y = grid_xyz[3 * (tid * NXG) + 1];
        float z = grid_xyz[3 * tid + 2];
        xs2[tid] = __fmul_rn(x, x);
        ys2[tid] = __fmul_rn(y, y);
        zz[tid]  = __fmul_rn(z, z);
    }
    __syncthreads();

    // ---------------- Phase 1: stream density, build per-row argmax ----------
    for (int c = 0; c < NCHUNK; c++) {
        const int r0    = c * CHUNK_ROWS;
        const int nrows = min(CHUNK_ROWS, NROWS - r0);
        const int nelem = nrows * NXG;
        const float* src = density + base + (size_t)r0 * NXG;
        #pragma unroll 8
        for (int idx = tid; idx < nelem; idx += 256)
            buf[idx] = __ldg(&src[idx]);
        __syncthreads();

        if (tid < nrows) {
            const int r = r0 + tid;
            const int i = r / NXG;
            const int j = r % NXG;
            const float t2 = __fadd_rn(xs2[i], ys2[j]);
            const float* row = buf + tid * NXG;   // stride-41 words: conflict-free
            float best = NEGF; int bk = 0;
            #pragma unroll
            for (int k = 0; k < NXG; k++) {
                const float s = __fadd_rn(t2, zz[k]);
                const float v = (s <= 36.0f) ? row[k] : NEGF;
                if (v > best) { best = v; bk = k; }   // strict >: first-k on ties
            }
            rowmax[r] = best;
            rowk[r]   = (uint8_t)bk;
        }
        __syncthreads();
    }

    // ---------------- Phase 2: K iterations of argmax + local NMS ------------
    int pk_i[KP], pk_j[KP], pk_k[KP];
    int npk = 0;   // replicated across threads (derived from shared data)

    for (int it = 0; it < KP; it++) {
        // Block argmax over rowmax[0..1680], first-occurrence tie-break.
        float bv = -__int_as_float(0x7f800000);
        int   br = 0x7fffffff;
        for (int r = tid; r < NROWS; r += 256) {
            float v = rowmax[r];
            if (v > bv) { bv = v; br = r; }        // r ascending: ties keep earlier
        }
        #pragma unroll
        for (int off = 16; off; off >>= 1) {
            float ov = __shfl_xor_sync(0xffffffffu, bv, off);
            int   orr = __shfl_xor_sync(0xffffffffu, br, off);
            if (ov > bv || (ov == bv && orr < br)) { bv = ov; br = orr; }
        }
        if (lane == 0) { swv[w] = bv; swr[w] = br; }
        __syncthreads();
        if (w == 0) {
            float v = (lane < 8) ? swv[lane] : -__int_as_float(0x7f800000);
            int   r = (lane < 8) ? swr[lane] : 0x7fffffff;
            #pragma unroll
            for (int off = 4; off; off >>= 1) {
                float ov = __shfl_xor_sync(0xffffffffu, v, off);
                int   orr = __shfl_xor_sync(0xffffffffu, r, off);
                if (ov > v || (ov == v && orr < r)) { v = ov; r = orr; }
            }
            if (lane == 0) *s_pick = r;
        }
        __syncthreads();

        const int   pr  = *s_pick;
        const float sc  = rowmax[pr];
        const int   pkk = (int)rowk[pr];
        const int   pi  = pr / NXG;
        const int   pj  = pr % NXG;
        const bool  valid = sc > VTH;

        if (tid == 0) {
            s_ps[it] = sc;
            s_pg[it] = pr * NXG + pkk;
            s_pv[it] = valid ? 1 : 0;
        }
        if (valid) { pk_i[npk] = pi; pk_j[npk] = pj; pk_k[npk] = pkk; npk++; }
        __syncthreads();   // everyone done reading rowmax before rewrite

        if (it == KP - 1) break;

        // Recompute rows intersecting the new peak's Chebyshev ball, applying
        // suppression from ALL picked-so-far peaks. Thread-per-row, serial scan.
        if (valid) {
            const int i0 = max(pi - SEP, 0), i1 = min(pi + SEP, NXG - 1);
            const int j0 = max(pj - SEP, 0), j1 = min(pj + SEP, NXG - 1);
            const int nj = j1 - j0 + 1;
            const int nr = (i1 - i0 + 1) * nj;
            if (tid < nr) {
                const int i = i0 + tid / nj;
                const int j = j0 + tid % nj;
                const int r = i * NXG + j;
                const float t2 = __fadd_rn(xs2[i], ys2[j]);
                const float* rowg = density + base + (size_t)r * NXG;

                // Which peaks' balls contain this (i,j) column?
                bool in0 = 0 < npk && abs(i - pk_i[0]) <= SEP && abs(j - pk_j[0]) <= SEP;
                bool in1 = 1 < npk && abs(i - pk_i[1]) <= SEP && abs(j - pk_j[1]) <= SEP;
                bool in2 = 2 < npk && abs(i - pk_i[2]) <= SEP && abs(j - pk_j[2]) <= SEP;

                float best = NEGF; int bk = 0;
                #pragma unroll
                for (int k = 0; k < NXG; k++) {
                    const float dv = __ldg(&rowg[k]);   // unconditional: enables MLP
                    const float s  = __fadd_rn(t2, zz[k]);
                    bool sup = (s > 36.0f);
                    if (in0 && abs(k - pk_k[0]) <= SEP) sup = true;
                    if (in1 && abs(k - pk_k[1]) <= SEP) sup = true;
                    if (in2 && abs(k - pk_k[2]) <= SEP) sup = true;
                    const float v = sup ? NEGF : dv;
                    if (v > best) { best = v; bk = k; }
                }
                rowmax[r] = best;
                rowk[r]   = (uint8_t)bk;
            }
        }
        __syncthreads();
    }

    // ---------------- Epilogue: transform + write outputs --------------------
    // Output layout: coords_local [NC,K,3] | coords_global [NC,K,3] |
    //                scores [NC,K] | mask [NC,K]  (all float32)
    if (tid < KP) {
        const int kk = tid;
        const int p  = blockIdx.x;
        const int n  = p / C;
        const int NC = gridDim.x;

        const float sc    = s_ps[kk];
        const bool  valid = (s_pv[kk] != 0);
        const int   g     = s_pg[kk];

        float x = 0.f, y = 0.f, z = 0.f;
        if (valid) {
            x = grid_xyz[3 * g + 0];
            y = grid_xyz[3 * g + 1];
            z = grid_xyz[3 * g + 2];
        }
        const float nm = node_mask[n];
        const float* R = Rmats + (size_t)n * 9;
        const float* t = tpos  + (size_t)n * 3;
        const float gx = R[0] * x + R[1] * y + R[2] * z + t[0];
        const float gy = R[3] * x + R[4] * y + R[5] * z + t[1];
        const float gz = R[6] * x + R[7] * y + R[8] * z + t[2];

        float* CL = out;
        float* CG = out + (size_t)NC * KP * 3;
        float* SC = out + (size_t)NC * KP * 6;
        float* MS = SC  + (size_t)NC * KP;

        const size_t o3 = ((size_t)p * KP + kk) * 3;
        CL[o3 + 0] = x * nm;  CL[o3 + 1] = y * nm;  CL[o3 + 2] = z * nm;
        CG[o3 + 0] = gx * nm; CG[o3 + 1] = gy * nm; CG[o3 + 2] = gz * nm;
        SC[(size_t)p * KP + kk] = (valid ? sc : NEGF) * nm;
        MS[(size_t)p * KP + kk] = (valid && nm != 0.0f) ? 1.0f : 0.0f;
    }
}

extern "C" void kernel_launch(void* const* d_in, const int* in_sizes, int n_in,
                              void* d_out, int out_size)
{
    // Input order per reference setup_inputs():
    // 0: density [B,N,C,G] f32   1: grid_xyz [G,3] f32   2: sphere_mask (unused)
    // 3: coords_int (unused)     4: Rmats [B,N,3,3] f32  5: tpos [B,N,3] f32
    // 6: node_mask [B,N] f32
    const float* density   = (const float*)d_in[0];
    const float* grid_xyz  = (const float*)d_in[1];
    const float* Rmats     = (const float*)d_in[4];
    const float* tposp     = (const float*)d_in[5];
    const float* node_mask = (const float*)d_in[6];
    float* out = (float*)d_out;

    const int NC = in_sizes[0] / GVOX;      // B*N*C = 512
    const int N  = in_sizes[4] / 9;         // B*N   = 128
    const int C  = NC / N;                  // 4
    (void)n_in; (void)out_size;

    static int smem_set = 0;
    if (!smem_set) {
        cudaFuncSetAttribute(fused_peaks_kernel,
                             cudaFuncAttributeMaxDynamicSharedMemorySize, SM_TOTAL);
        smem_set = 1;
    }
    fused_peaks_kernel<<<NC, 256, SM_TOTAL>>>(density, grid_xyz, Rmats, tposp,
                                              node_mask, out, C);
}

// round 4
// speedup vs baseline: 3.3133x; 1.1474x over previous
#include <cuda_runtime.h>
#include <stdint.h>

// Problem constants (fixed by the reference: NX=41, r_max=6.0, voxel=0.3, K=4, min_sep=3)
#define NXG    41
#define NROWS  (NXG * NXG)       // 1681 rows of 41 voxels
#define GVOX   (NXG * NXG * NXG) // 68921
#define KP     4
#define SEP    3
#define NEGF   (-1.0e9f)
#define VTH    (-1.0e8f)

#define CH      128                          // rows per chunk
#define CHF     (CH * NXG)                   // 5248 floats per full chunk
#define NCHUNK  ((NROWS + CH - 1) / CH)      // 14
#define BUFF    (CHF + 4)                    // +4 floats alignment slack

// Shared-memory layout (bytes)
#define SM_BUF0   0
#define SM_BUF1   (SM_BUF0 + BUFF * 4)               // 21008
#define SM_ROWMAX (SM_BUF1 + BUFF * 4)               // 42016
#define SM_ROWK   (SM_ROWMAX + NROWS * 4)            // 48740
#define SM_XS2    (SM_ROWK + 1684)                   // 50424
#define SM_YS2    (SM_XS2 + 168)
#define SM_ZZ     (SM_YS2 + 168)
#define SM_SWV    (SM_ZZ + 168)
#define SM_SWR    (SM_SWV + 32)
#define SM_PICK   (SM_SWR + 32)
#define SM_PS     (SM_PICK + 4)
#define SM_PG     (SM_PS + 16)
#define SM_PV     (SM_PG + 16)
#define SM_TOTAL  (SM_PV + 16 + 28)                  // ~51.1 KB -> 4 CTAs/SM

#define CP_ASYNC_16(dst, src) \
    asm volatile("cp.async.cg.shared.global [%0], [%1], 16;" :: "r"(dst), "l"(src) : "memory")
#define CP_ASYNC_4(dst, src) \
    asm volatile("cp.async.ca.shared.global [%0], [%1], 4;"  :: "r"(dst), "l"(src) : "memory")
#define CP_COMMIT()  asm volatile("cp.async.commit_group;" ::: "memory")
#define CP_WAIT(n)   asm volatile("cp.async.wait_group %0;" :: "n"(n) : "memory")

static __device__ __forceinline__ uint32_t smem_u32(const void* p) {
    return (uint32_t)__cvta_generic_to_shared(p);
}

// Issue one chunk's loads: h-scalar head (reaches 16B alignment), 16B body,
// scalar tail. dstb = byte smem addr of buffer start; s = float shift so the
// SMEM side stays 16B-aligned where the global side is.
static __device__ __forceinline__ void issue_chunk(uint32_t dstb, const float* g0,
                                                   int nelem, int h, int s)
{
    const int tid = threadIdx.x;
    if (tid < h) CP_ASYNC_4(dstb + (uint32_t)(s + tid) * 4u, g0 + tid);
    const int body = nelem - h;
    const int nv = body >> 2;
    for (int vi = tid; vi < nv; vi += 256) {
        const int f = h + 4 * vi;
        CP_ASYNC_16(dstb + (uint32_t)(s + f) * 4u, g0 + f);
    }
    const int nrem = body & 3;
    if (tid < nrem) {
        const int f = h + 4 * nv + tid;
        CP_ASYNC_4(dstb + (uint32_t)(s + f) * 4u, g0 + f);
    }
}

// ---------------------------------------------------------------------------
// Fully fused, cp.async double-buffered. One CTA per (n,c) problem.
__global__ __launch_bounds__(256, 4)
void fused_peaks_kernel(const float* __restrict__ density,
                        const float* __restrict__ grid_xyz,
                        const float* __restrict__ Rmats,
                        const float* __restrict__ tpos,
                        const float* __restrict__ node_mask,
                        float* __restrict__ out,
                        int C)
{
    extern __shared__ char smem[];
    float*   buf[2];
    buf[0] = (float*)(smem + SM_BUF0);
    buf[1] = (float*)(smem + SM_BUF1);
    float*   rowmax = (float*)(smem + SM_ROWMAX);
    uint8_t* rowk   = (uint8_t*)(smem + SM_ROWK);
    float*   xs2    = (float*)(smem + SM_XS2);
    float*   ys2    = (float*)(smem + SM_YS2);
    float*   zz     = (float*)(smem + SM_ZZ);
    float*   swv    = (float*)(smem + SM_SWV);
    int*     swr    = (int*)(smem + SM_SWR);
    int*     s_pick = (int*)(smem + SM_PICK);
    float*   s_ps   = (float*)(smem + SM_PS);
    int*     s_pg   = (int*)(smem + SM_PG);
    int*     s_pv   = (int*)(smem + SM_PV);

    const int tid  = threadIdx.x;
    const int lane = tid & 31;
    const int w    = tid >> 5;
    const int p    = blockIdx.x;
    const size_t base = (size_t)p * GVOX;
    const int sft = p & 3;                 // SMEM float shift
    const int h   = (4 - sft) & 3;         // scalar head count

    // Per-axis squared-coordinate tables from the ACTUAL grid_xyz input.
    // Sphere test (s<=36.0f) is bit-equivalent to sqrtf(s)<=6.0f under RN.
    if (tid < NXG) {
        float x = grid_xyz[3 * (tid * NXG * NXG) + 0];
        float y = grid_xyz[3 * (tid * NXG) + 1];
        float z = grid_xyz[3 * tid + 2];
        xs2[tid] = __fmul_rn(x, x);
        ys2[tid] = __fmul_rn(y, y);
        zz[tid]  = __fmul_rn(z, z);
    }

    // ---------------- Phase 1: double-buffered stream + per-row argmax -------
    issue_chunk(smem_u32(buf[0]), density + base, CHF, h, sft);
    CP_COMMIT();

    for (int c = 0; c < NCHUNK; c++) {
        const int next = c + 1;
        if (next < NCHUNK) {
            const int ne = min(CHF, GVOX - next * CHF);
            issue_chunk(smem_u32(buf[next & 1]), density + base + (size_t)next * CHF,
                        ne, h, sft);
            CP_COMMIT();
            CP_WAIT(1);
        } else {
            CP_WAIT(0);
        }
        __syncthreads();   // chunk c visible to all; also covers table init at c=0

        // Thread-pair per row: even lane scans k in [0,21), odd k in [21,41).
        const int r0      = c * CH;
        const int nrows_c = min(CH, NROWS - r0);
        const int lr      = tid >> 1;
        const int half    = tid & 1;
        const int r       = min(r0 + lr, NROWS - 1);
        const int i       = r / NXG;
        const int j       = r - i * NXG;
        const float t2    = __fadd_rn(xs2[i], ys2[j]);
        const float* rowp = buf[c & 1] + sft + lr * NXG + half * 21;
        const int kb      = half * 21;
        const int cnt     = half ? 20 : 21;

        float best = NEGF; int bk = kb;
        #pragma unroll
        for (int kk = 0; kk < 21; kk++) {
            if (kk < cnt) {
                const int k = kb + kk;
                const float sv = __fadd_rn(t2, zz[k]);
                const float v  = (sv <= 36.0f) ? rowp[kk] : NEGF;
                if (v > best) { best = v; bk = k; }   // strict >: first-k on ties
            }
        }
        // Merge halves (odd ks all > even ks, so strict > keeps lower k on ties)
        const float vo = __shfl_down_sync(0xffffffffu, best, 1);
        const int   ko = __shfl_down_sync(0xffffffffu, bk, 1);
        if (half == 0 && lr < nrows_c) {
            if (vo > best) { best = vo; bk = ko; }
            rowmax[r0 + lr] = best;
            rowk[r0 + lr]   = (uint8_t)bk;
        }
        __syncthreads();   // reduce done before buf[c&1] is overwritten
    }

    // ---------------- Phase 2: K iterations of argmax + local NMS ------------
    int pk_i[KP], pk_j[KP], pk_k[KP];
    int npk = 0;   // replicated across threads (derived from shared data)

    for (int it = 0; it < KP; it++) {
        // Block argmax over rowmax[0..1680], first-occurrence tie-break.
        float bv = -__int_as_float(0x7f800000);
        int   br = 0x7fffffff;
        for (int r = tid; r < NROWS; r += 256) {
            float v = rowmax[r];
            if (v > bv) { bv = v; br = r; }        // r ascending: ties keep earlier
        }
        #pragma unroll
        for (int off = 16; off; off >>= 1) {
            float ov = __shfl_xor_sync(0xffffffffu, bv, off);
            int   orr = __shfl_xor_sync(0xffffffffu, br, off);
            if (ov > bv || (ov == bv && orr < br)) { bv = ov; br = orr; }
        }
        if (lane == 0) { swv[w] = bv; swr[w] = br; }
        __syncthreads();
        if (w == 0) {
            float v = (lane < 8) ? swv[lane] : -__int_as_float(0x7f800000);
            int   r = (lane < 8) ? swr[lane] : 0x7fffffff;
            #pragma unroll
            for (int off = 4; off; off >>= 1) {
                float ov = __shfl_xor_sync(0xffffffffu, v, off);
                int   orr = __shfl_xor_sync(0xffffffffu, r, off);
                if (ov > v || (ov == v && orr < r)) { v = ov; r = orr; }
            }
            if (lane == 0) *s_pick = r;
        }
        __syncthreads();

        const int   pr  = *s_pick;
        const float sc  = rowmax[pr];
        const int   pkk = (int)rowk[pr];
        const int   pi  = pr / NXG;
        const int   pj  = pr % NXG;
        const bool  valid = sc > VTH;

        if (tid == 0) {
            s_ps[it] = sc;
            s_pg[it] = pr * NXG + pkk;
            s_pv[it] = valid ? 1 : 0;
        }
        if (valid) { pk_i[npk] = pi; pk_j[npk] = pj; pk_k[npk] = pkk; npk++; }
        __syncthreads();   // everyone done reading rowmax before rewrite

        if (it == KP - 1) break;

        // Recompute rows intersecting the new peak's Chebyshev ball, applying
        // suppression from ALL picked-so-far peaks. Thread-per-row, serial scan.
        if (valid) {
            const int i0 = max(pi - SEP, 0), i1 = min(pi + SEP, NXG - 1);
            const int j0 = max(pj - SEP, 0), j1 = min(pj + SEP, NXG - 1);
            const int nj = j1 - j0 + 1;
            const int nr = (i1 - i0 + 1) * nj;
            if (tid < nr) {
                const int i = i0 + tid / nj;
                const int j = j0 + tid % nj;
                const int r = i * NXG + j;
                const float t2 = __fadd_rn(xs2[i], ys2[j]);
                const float* rowg = density + base + (size_t)r * NXG;

                // Which peaks' balls contain this (i,j) column?
                bool in0 = 0 < npk && abs(i - pk_i[0]) <= SEP && abs(j - pk_j[0]) <= SEP;
                bool in1 = 1 < npk && abs(i - pk_i[1]) <= SEP && abs(j - pk_j[1]) <= SEP;
                bool in2 = 2 < npk && abs(i - pk_i[2]) <= SEP && abs(j - pk_j[2]) <= SEP;

                float best = NEGF; int bk = 0;
                #pragma unroll
                for (int k = 0; k < NXG; k++) {
                    const float dv = __ldg(&rowg[k]);   // unconditional: enables MLP
                    const float s  = __fadd_rn(t2, zz[k]);
                    bool sup = (s > 36.0f);
                    if (in0 && abs(k - pk_k[0]) <= SEP) sup = true;
                    if (in1 && abs(k - pk_k[1]) <= SEP) sup = true;
                    if (in2 && abs(k - pk_k[2]) <= SEP) sup = true;
                    const float v = sup ? NEGF : dv;
                    if (v > best) { best = v; bk = k; }
                }
                rowmax[r] = best;
                rowk[r]   = (uint8_t)bk;
            }
        }
        __syncthreads();
    }

    // ---------------- Epilogue: transform + write outputs --------------------
    // Output layout: coords_local [NC,K,3] | coords_global [NC,K,3] |
    //                scores [NC,K] | mask [NC,K]  (all float32)
    if (tid < KP) {
        const int kk = tid;
        const int n  = p / C;
        const int NC = gridDim.x;

        const float sc    = s_ps[kk];
        const bool  valid = (s_pv[kk] != 0);
        const int   g     = s_pg[kk];

        float x = 0.f, y = 0.f, z = 0.f;
        if (valid) {
            x = grid_xyz[3 * g + 0];
            y = grid_xyz[3 * g + 1];
            z = grid_xyz[3 * g + 2];
        }
        const float nm = node_mask[n];
        const float* R = Rmats + (size_t)n * 9;
        const float* t = tpos  + (size_t)n * 3;
        const float gx = R[0] * x + R[1] * y + R[2] * z + t[0];
        const float gy = R[3] * x + R[4] * y + R[5] * z + t[1];
        const float gz = R[6] * x + R[7] * y + R[8] * z + t[2];

        float* CL = out;
        float* CG = out + (size_t)NC * KP * 3;
        float* SC = out + (size_t)NC * KP * 6;
        float* MS = SC  + (size_t)NC * KP;

        const size_t o3 = ((size_t)p * KP + kk) * 3;
        CL[o3 + 0] = x * nm;  CL[o3 + 1] = y * nm;  CL[o3 + 2] = z * nm;
        CG[o3 + 0] = gx * nm; CG[o3 + 1] = gy * nm; CG[o3 + 2] = gz * nm;
        SC[(size_t)p * KP + kk] = (valid ? sc : NEGF) * nm;
        MS[(size_t)p * KP + kk] = (valid && nm != 0.0f) ? 1.0f : 0.0f;
    }
}

extern "C" void kernel_launch(void* const* d_in, const int* in_sizes, int n_in,
                              void* d_out, int out_size)
{
    // Input order per reference setup_inputs():
    // 0: density [B,N,C,G] f32   1: grid_xyz [G,3] f32   2: sphere_mask (unused)
    // 3: coords_int (unused)     4: Rmats [B,N,3,3] f32  5: tpos [B,N,3] f32
    // 6: node_mask [B,N] f32
    const float* density   = (const float*)d_in[0];
    const float* grid_xyz  = (const float*)d_in[1];
    const float* Rmats     = (const float*)d_in[4];
    const float* tposp     = (const float*)d_in[5];
    const float* node_mask = (const float*)d_in[6];
    float* out = (float*)d_out;

    const int NC = in_sizes[0] / GVOX;      // B*N*C = 512
    const int N  = in_sizes[4] / 9;         // B*N   = 128
    const int C  = NC / N;                  // 4
    (void)n_in; (void)out_size;

    static int smem_set = 0;
    if (!smem_set) {
        cudaFuncSetAttribute(fused_peaks_kernel,
                             cudaFuncAttributeMaxDynamicSharedMemorySize, SM_TOTAL);
        smem_set = 1;
    }
    fused_peaks_kernel<<<NC, 256, SM_TOTAL>>>(density, grid_xyz, Rmats, tposp,
                                              node_mask, out, C);
}

// round 5
// speedup vs baseline: 3.4314x; 1.0357x over previous
#include <cuda_runtime.h>
#include <stdint.h>

// Problem constants (fixed by the reference: NX=41, r_max=6.0, voxel=0.3, K=4, min_sep=3)
#define NXG    41
#define NROWS  (NXG * NXG)       // 1681 rows of 41 voxels
#define GVOX   (NXG * NXG * NXG) // 68921
#define KP     4
#define SEP    3
#define NEGF   (-1.0e9f)
#define VTH    (-1.0e8f)

#define WCH        16                         // rows per warp-chunk
#define WBUF       (WCH * NXG + 4)            // 660 floats (4 slack for align shift)
#define NWARP      8

// Shared-memory layout (bytes)
#define SM_BUF    0                                   // 8 warps * 2 stages * 660 f
#define SM_ROWMAX (SM_BUF + NWARP * 2 * WBUF * 4)     // 42240
#define SM_ROWK   (SM_ROWMAX + NROWS * 4)             // 48964
#define SM_XS2    (SM_ROWK + 1684)                    // 50648
#define SM_YS2    (SM_XS2 + 168)
#define SM_ZZ     (SM_YS2 + 168)
#define SM_SWV    (SM_ZZ + 168)
#define SM_SWR    (SM_SWV + 32)
#define SM_PICK   (SM_SWR + 32)
#define SM_PS     (SM_PICK + 4)
#define SM_PG     (SM_PS + 16)
#define SM_PV     (SM_PG + 16)
#define SM_TOTAL  (SM_PV + 16 + 28)                   // ~51.3 KB -> 4 CTAs/SM

#define CP_ASYNC_16(dst, src) \
    asm volatile("cp.async.cg.shared.global [%0], [%1], 16;" :: "r"(dst), "l"(src) : "memory")
#define CP_ASYNC_4(dst, src) \
    asm volatile("cp.async.ca.shared.global [%0], [%1], 4;"  :: "r"(dst), "l"(src) : "memory")
#define CP_COMMIT()  asm volatile("cp.async.commit_group;" ::: "memory")
#define CP_WAIT(n)   asm volatile("cp.async.wait_group %0;" :: "n"(n) : "memory")

static __device__ __forceinline__ uint32_t smem_u32(const void* p) {
    return (uint32_t)__cvta_generic_to_shared(p);
}

// Exact floor(r/41) for 0 <= r < 53773.
static __device__ __forceinline__ int div41(int r) {
    return (int)(((unsigned)r * 51151u) >> 21);
}

// Issue one warp-chunk: h-scalar head to reach 16B global alignment, 16B body,
// scalar tail. dstb = smem byte addr of buffer; sft = float shift matching h.
static __device__ __forceinline__ void issue_wchunk(uint32_t dstb, const float* g0,
                                                    int nelem, int h, int sft, int lane)
{
    if (lane < h) CP_ASYNC_4(dstb + (uint32_t)(sft + lane) * 4u, g0 + lane);
    const int body = nelem - h;
    const int nv = body >> 2;
    for (int vi = lane; vi < nv; vi += 32) {
        const int f = h + 4 * vi;
        CP_ASYNC_16(dstb + (uint32_t)(sft + f) * 4u, g0 + f);
    }
    const int nrem = body & 3;
    if (lane < nrem) {
        const int f = h + 4 * nv + lane;
        CP_ASYNC_4(dstb + (uint32_t)(sft + f) * 4u, g0 + f);
    }
}

// ---------------------------------------------------------------------------
// Fully fused, warp-decoupled double-buffered streaming. One CTA per (n,c).
__global__ __launch_bounds__(256, 4)
void fused_peaks_kernel(const float* __restrict__ density,
                        const float* __restrict__ grid_xyz,
                        const float* __restrict__ Rmats,
                        const float* __restrict__ tpos,
                        const float* __restrict__ node_mask,
                        float* __restrict__ out,
                        int C)
{
    extern __shared__ char smem[];
    float*   bufs   = (float*)(smem + SM_BUF);
    float*   rowmax = (float*)(smem + SM_ROWMAX);
    uint8_t* rowk   = (uint8_t*)(smem + SM_ROWK);
    float*   xs2    = (float*)(smem + SM_XS2);
    float*   ys2    = (float*)(smem + SM_YS2);
    float*   zz     = (float*)(smem + SM_ZZ);
    float*   swv    = (float*)(smem + SM_SWV);
    int*     swr    = (int*)(smem + SM_SWR);
    int*     s_pick = (int*)(smem + SM_PICK);
    float*   s_ps   = (float*)(smem + SM_PS);
    int*     s_pg   = (int*)(smem + SM_PG);
    int*     s_pv   = (int*)(smem + SM_PV);

    const int tid  = threadIdx.x;
    const int lane = tid & 31;
    const int w    = tid >> 5;
    const int p    = blockIdx.x;
    const size_t base = (size_t)p * GVOX;   // GVOX % 4 == 1 -> base % 4 == p % 4

    // Warp-private row range and buffers.
    const int rstart = (w * NROWS) >> 3;          // NROWS not mult of 8: ranges via shifts
    const int rend   = ((w + 1) * NROWS) >> 3;
    const int nch    = (rend - rstart + WCH - 1) / WCH;
    float* wb[2] = { bufs + (w * 2 + 0) * WBUF, bufs + (w * 2 + 1) * WBUF };

    // Chunk geometry helper values (computed per chunk below):
    //   row0, nelem, global ptr, alignment (al) -> head h, smem shift sft.

    // Kick off chunk 0 for this warp immediately.
    {
        const int row0  = rstart;
        const int nrows = min(WCH, rend - row0);
        const long off  = (long)row0 * NXG;
        const int  al   = (int)((base + off) & 3);
        issue_wchunk(smem_u32(wb[0]), density + base + off, nrows * NXG,
                     (4 - al) & 3, al, lane);
        CP_COMMIT();
    }

    // Per-axis squared-coordinate tables from the ACTUAL grid_xyz input.
    // Sphere test (s<=36.0f) is bit-equivalent to sqrtf(s)<=6.0f under RN.
    if (tid < NXG) {
        float x = grid_xyz[3 * (tid * NXG * NXG) + 0];
        float y = grid_xyz[3 * (tid * NXG) + 1];
        float z = grid_xyz[3 * tid + 2];
        xs2[tid] = __fmul_rn(x, x);
        ys2[tid] = __fmul_rn(y, y);
        zz[tid]  = __fmul_rn(z, z);
    }
    __syncthreads();   // tables visible to all warps (overlapped with chunk-0 DMA)

    // ---------------- Phase 1: per-warp double-buffered stream + argmax ------
    for (int c = 0; c < nch; c++) {
        const int next = c + 1;
        if (next < nch) {
            const int row0n  = rstart + next * WCH;
            const int nrowsn = min(WCH, rend - row0n);
            const long offn  = (long)row0n * NXG;
            const int  aln   = (int)((base + offn) & 3);
            issue_wchunk(smem_u32(wb[next & 1]), density + base + offn,
                         nrowsn * NXG, (4 - aln) & 3, aln, lane);
            CP_COMMIT();
            CP_WAIT(1);
        } else {
            CP_WAIT(0);
        }
        __syncwarp();   // cross-lane visibility of chunk c data

        // Thread-pair per row: even lane scans k in [0,21), odd k in [21,41).
        const int row0  = rstart + c * WCH;
        const int nrows = min(WCH, rend - row0);
        const int al    = (int)((base + (long)row0 * NXG) & 3);
        const int lr    = lane >> 1;                 // 0..15
        const int half  = lane & 1;
        const int r     = min(row0 + lr, NROWS - 1);
        const int i     = div41(r);
        const int j     = r - i * NXG;
        const float t2  = __fadd_rn(xs2[i], ys2[j]);
        const float* rowp = wb[c & 1] + al + lr * NXG + half * 21;
        const int kb    = half * 21;
        const int cnt   = half ? 20 : 21;

        float best = NEGF; int bk = kb;
        #pragma unroll
        for (int kk = 0; kk < 21; kk++) {
            if (kk < cnt) {
                const int k = kb + kk;
                const float sv = __fadd_rn(t2, zz[k]);
                const float v  = (sv <= 36.0f) ? rowp[kk] : NEGF;
                if (v > best) { best = v; bk = k; }   // strict >: first-k on ties
            }
        }
        // Merge halves (odd ks all > even ks, so strict > keeps lower k on ties)
        const float vo = __shfl_down_sync(0xffffffffu, best, 1);
        const int   ko = __shfl_down_sync(0xffffffffu, bk, 1);
        if (half == 0 && lr < nrows) {
            if (vo > best) { best = vo; bk = ko; }
            rowmax[row0 + lr] = best;
            rowk[row0 + lr]   = (uint8_t)bk;
        }
        __syncwarp();   // all lanes done with buf[c&1] before it is refilled
    }
    __syncthreads();    // all warps' rowmax/rowk complete

    // ---------------- Phase 2: K iterations of argmax + local NMS ------------
    int pk_i[KP], pk_j[KP], pk_k[KP];
    int npk = 0;   // replicated across threads (derived from shared data)

    for (int it = 0; it < KP; it++) {
        // Block argmax over rowmax[0..1680], first-occurrence tie-break.
        float bv = -__int_as_float(0x7f800000);
        int   br = 0x7fffffff;
        for (int r = tid; r < NROWS; r += 256) {
            float v = rowmax[r];
            if (v > bv) { bv = v; br = r; }        // r ascending: ties keep earlier
        }
        #pragma unroll
        for (int off = 16; off; off >>= 1) {
            float ov = __shfl_xor_sync(0xffffffffu, bv, off);
            int   orr = __shfl_xor_sync(0xffffffffu, br, off);
            if (ov > bv || (ov == bv && orr < br)) { bv = ov; br = orr; }
        }
        if (lane == 0) { swv[w] = bv; swr[w] = br; }
        __syncthreads();
        if (w == 0) {
            float v = (lane < 8) ? swv[lane] : -__int_as_float(0x7f800000);
            int   r = (lane < 8) ? swr[lane] : 0x7fffffff;
            #pragma unroll
            for (int off = 4; off; off >>= 1) {
                float ov = __shfl_xor_sync(0xffffffffu, v, off);
                int   orr = __shfl_xor_sync(0xffffffffu, r, off);
                if (ov > v || (ov == v && orr < r)) { v = ov; r = orr; }
            }
            if (lane == 0) *s_pick = r;
        }
        __syncthreads();

        const int   pr  = *s_pick;
        const float sc  = rowmax[pr];
        const int   pkk = (int)rowk[pr];
        const int   pi  = div41(pr);
        const int   pj  = pr - pi * NXG;
        const bool  valid = sc > VTH;

        if (tid == 0) {
            s_ps[it] = sc;
            s_pg[it] = pr * NXG + pkk;
            s_pv[it] = valid ? 1 : 0;
        }
        if (valid) { pk_i[npk] = pi; pk_j[npk] = pj; pk_k[npk] = pkk; npk++; }
        __syncthreads();   // everyone done reading rowmax before rewrite

        if (it == KP - 1) break;

        // Recompute rows intersecting the new peak's Chebyshev ball, applying
        // suppression from ALL picked-so-far peaks. Thread-per-row, serial scan.
        if (valid) {
            const int i0 = max(pi - SEP, 0), i1 = min(pi + SEP, NXG - 1);
            const int j0 = max(pj - SEP, 0), j1 = min(pj + SEP, NXG - 1);
            const int nj = j1 - j0 + 1;
            const int nr = (i1 - i0 + 1) * nj;
            if (tid < nr) {
                const int i = i0 + tid / nj;
                const int j = j0 + tid % nj;
                const int r = i * NXG + j;
                const float t2 = __fadd_rn(xs2[i], ys2[j]);
                const float* rowg = density + base + (size_t)r * NXG;

                // Which peaks' balls contain this (i,j) column?
                bool in0 = 0 < npk && abs(i - pk_i[0]) <= SEP && abs(j - pk_j[0]) <= SEP;
                bool in1 = 1 < npk && abs(i - pk_i[1]) <= SEP && abs(j - pk_j[1]) <= SEP;
                bool in2 = 2 < npk && abs(i - pk_i[2]) <= SEP && abs(j - pk_j[2]) <= SEP;

                float best = NEGF; int bk = 0;
                #pragma unroll
                for (int k = 0; k < NXG; k++) {
                    const float dv = __ldg(&rowg[k]);   // unconditional: enables MLP
                    const float s  = __fadd_rn(t2, zz[k]);
                    bool sup = (s > 36.0f);
                    if (in0 && abs(k - pk_k[0]) <= SEP) sup = true;
                    if (in1 && abs(k - pk_k[1]) <= SEP) sup = true;
                    if (in2 && abs(k - pk_k[2]) <= SEP) sup = true;
                    const float v = sup ? NEGF : dv;
                    if (v > best) { best = v; bk = k; }
                }
                rowmax[r] = best;
                rowk[r]   = (uint8_t)bk;
            }
        }
        __syncthreads();
    }

    // ---------------- Epilogue: transform + write outputs --------------------
    // Output layout: coords_local [NC,K,3] | coords_global [NC,K,3] |
    //                scores [NC,K] | mask [NC,K]  (all float32)
    if (tid < KP) {
        const int kk = tid;
        const int n  = p / C;
        const int NC = gridDim.x;

        const float sc    = s_ps[kk];
        const bool  valid = (s_pv[kk] != 0);
        const int   g     = s_pg[kk];

        float x = 0.f, y = 0.f, z = 0.f;
        if (valid) {
            x = grid_xyz[3 * g + 0];
            y = grid_xyz[3 * g + 1];
            z = grid_xyz[3 * g + 2];
        }
        const float nm = node_mask[n];
        const float* R = Rmats + (size_t)n * 9;
        const float* t = tpos  + (size_t)n * 3;
        const float gx = R[0] * x + R[1] * y + R[2] * z + t[0];
        const float gy = R[3] * x + R[4] * y + R[5] * z + t[1];
        const float gz = R[6] * x + R[7] * y + R[8] * z + t[2];

        float* CL = out;
        float* CG = out + (size_t)NC * KP * 3;
        float* SC = out + (size_t)NC * KP * 6;
        float* MS = SC  + (size_t)NC * KP;

        const size_t o3 = ((size_t)p * KP + kk) * 3;
        CL[o3 + 0] = x * nm;  CL[o3 + 1] = y * nm;  CL[o3 + 2] = z * nm;
        CG[o3 + 0] = gx * nm; CG[o3 + 1] = gy * nm; CG[o3 + 2] = gz * nm;
        SC[(size_t)p * KP + kk] = (valid ? sc : NEGF) * nm;
        MS[(size_t)p * KP + kk] = (valid && nm != 0.0f) ? 1.0f : 0.0f;
    }
}

extern "C" void kernel_launch(void* const* d_in, const int* in_sizes, int n_in,
                              void* d_out, int out_size)
{
    // Input order per reference setup_inputs():
    // 0: density [B,N,C,G] f32   1: grid_xyz [G,3] f32   2: sphere_mask (unused)
    // 3: coords_int (unused)     4: Rmats [B,N,3,3] f32  5: tpos [B,N,3] f32
    // 6: node_mask [B,N] f32
    const float* density   = (const float*)d_in[0];
    const float* grid_xyz  = (const float*)d_in[1];
    const float* Rmats     = (const float*)d_in[4];
    const float* tposp     = (const float*)d_in[5];
    const float* node_mask = (const float*)d_in[6];
    float* out = (float*)d_out;

    const int NC = in_sizes[0] / GVOX;      // B*N*C = 512
    const int N  = in_sizes[4] / 9;         // B*N   = 128
    const int C  = NC / N;                  // 4
    (void)n_in; (void)out_size;

    static int smem_set = 0;
    if (!smem_set) {
        cudaFuncSetAttribute(fused_peaks_kernel,
                             cudaFuncAttributeMaxDynamicSharedMemorySize, SM_TOTAL);
        smem_set = 1;
    }
    fused_peaks_kernel<<<NC, 256, SM_TOTAL>>>(density, grid_xyz, Rmats, tposp,
                                              node_mask, out, C);
}